// round 2
// baseline (speedup 1.0000x reference)
#include <cuda_runtime.h>
#include <math.h>

#define EPSV 1e-7f
#define PI_F 3.14159265358979323846f
#define MAXBN 12800
#define H 128

// scratch (static __device__ — no runtime allocation)
__device__ float g_R[MAXBN * 9];
__device__ float g_cv[MAXBN * 3];
__device__ float g_hsum[(size_t)MAXBN * H];

// ---------------------------------------------------------------------------
// Kernel A: per-node rotation matrix + canonical velocity
// ---------------------------------------------------------------------------
__global__ void node_prep(const float* __restrict__ inputs, int BN) {
    int idx = blockIdx.x * blockDim.x + threadIdx.x;
    if (idx >= BN) return;
    const float* x = inputs + (size_t)idx * 6;
    float vx = x[3], vy = x[4], vz = x[5];
    float rho = sqrtf(vx * vx + vy * vy + vz * vz);
    float theta = atan2f(vy, vx);
    float st, ct;
    sincosf(theta, &st, &ct);
    float cpin = fminf(fmaxf(vz / (rho + EPSV), -1.f), 1.f);
    float phi = acosf(cpin);
    float sp, cp;
    sincosf(phi, &sp, &cp);
    float R0 = cp * ct, R1 = -st, R2 = sp * ct;
    float R3 = cp * st, R4 = ct, R5 = sp * st;
    float R6 = -sp, R7 = 0.f, R8 = cp;
    float* Rg = g_R + (size_t)idx * 9;
    Rg[0] = R0; Rg[1] = R1; Rg[2] = R2;
    Rg[3] = R3; Rg[4] = R4; Rg[5] = R5;
    Rg[6] = R6; Rg[7] = R7; Rg[8] = R8;
    // canon_vel = R^T v
    float* cv = g_cv + (size_t)idx * 3;
    cv[0] = R0 * vx + R3 * vy + R6 * vz;
    cv[1] = R1 * vx + R4 * vy + R7 * vz;
    cv[2] = R2 * vx + R5 * vy + R8 * vz;
}

// ---------------------------------------------------------------------------
// Kernel B: per (b, recv node) block.  Phase 1: each thread computes the 12
// geometric features of one edge.  Phase 2: each thread owns one hidden
// channel t, accumulates sum_j silu(edge_attr @ W1 + b1)[t] over 99 edges.
// The recv node's rel_feat contribution to layer-1 preact is constant per
// block and folded into `base`.  W2 is applied later (linearity of the sum).
// ---------------------------------------------------------------------------
__global__ void edge_kernel(const float* __restrict__ inputs,
                            const float* __restrict__ W1,
                            const float* __restrict__ b1,
                            int N) {
    int bi = blockIdx.x;
    int b = bi / N;
    int i = bi - b * N;
    int t = threadIdx.x;

    __shared__ __align__(16) float se[127 * 12];

    const float* xi = inputs + (size_t)bi * 6;
    float pix = xi[0], piy = xi[1], piz = xi[2];
    const float* Ri = g_R + (size_t)bi * 9;
    float r0 = Ri[0], r1 = Ri[1], r2 = Ri[2];
    float r3 = Ri[3], r4 = Ri[4], r5 = Ri[5];
    float r6 = Ri[6], r7 = Ri[7], r8 = Ri[8];

    int Em = N - 1;
    if (t < Em) {
        int j = t + (t >= i ? 1 : 0);
        const float* xj = inputs + ((size_t)b * N + j) * 6;
        float relx = xj[0] - pix, rely = xj[1] - piy, relz = xj[2] - piz;
        // rot_rel = Ri^T rel
        float rrx = r0 * relx + r3 * rely + r6 * relz;
        float rry = r1 * relx + r4 * rely + r7 * relz;
        float rrz = r2 * relx + r5 * rely + r8 * relz;
        float dist = sqrtf(relx * relx + rely * rely + relz * relz);
        float rho_e = sqrtf(rrx * rrx + rry * rry + rrz * rrz);
        float theta_e = atan2f(rry, rrx);
        float phi_e = acosf(fminf(fmaxf(rrz / (rho_e + EPSV), -1.f), 1.f));
        const float* Rj = g_R + ((size_t)b * N + j) * 9;
        float q0 = Rj[0], q1 = Rj[1], q2 = Rj[2];
        float q3 = Rj[3], q4 = Rj[4], q5 = Rj[5];
        float q6 = Rj[6], q7 = Rj[7], q8 = Rj[8];
        // rot_or = Ri^T Rj ; need (0,0),(1,0),(2,0),(2,1),(2,2)
        float ro00 = r0 * q0 + r3 * q3 + r6 * q6;
        float ro10 = r1 * q0 + r4 * q3 + r7 * q6;
        float ro20 = r2 * q0 + r5 * q3 + r8 * q6;
        float ro21 = r2 * q1 + r5 * q4 + r8 * q7;
        float ro22 = r2 * q2 + r5 * q5 + r8 * q8;
        float e0 = atan2f(ro10, ro00) * (1.f / PI_F);
        float e1 = asinf(fminf(fmaxf(-ro20, -1.f), 1.f)) * (1.f / PI_F);
        float e2 = atan2f(ro21, ro22) * (1.f / PI_F);
        float vjx = xj[3], vjy = xj[4], vjz = xj[5];
        float rvx = r0 * vjx + r3 * vjy + r6 * vjz;
        float rvy = r1 * vjx + r4 * vjy + r7 * vjz;
        float rvz = r2 * vjx + r5 * vjy + r8 * vjz;
        float* s = se + t * 12;
        s[0] = rrx; s[1] = rry; s[2] = rrz;
        s[3] = e0;  s[4] = e1;  s[5] = e2;
        s[6] = dist; s[7] = theta_e; s[8] = phi_e;
        s[9] = rvx; s[10] = rvy; s[11] = rvz;
    }

    // per-channel W1 column in registers
    float w[12];
#pragma unroll
    for (int k = 0; k < 12; k++) w[k] = W1[k * H + t];
    const float* cv = g_cv + (size_t)bi * 3;
    float base = b1[t] + cv[0] * W1[15 * H + t] + cv[1] * W1[16 * H + t] +
                 cv[2] * W1[17 * H + t];

    __syncthreads();

    float hsum = 0.f;
    for (int je = 0; je < Em; je++) {
        const float4* s4 = (const float4*)(se + je * 12);
        float4 a = s4[0];
        float4 c = s4[1];
        float4 d = s4[2];
        float z = base;
        z += a.x * w[0] + a.y * w[1] + a.z * w[2] + a.w * w[3];
        z += c.x * w[4] + c.y * w[5] + c.z * w[6] + c.w * w[7];
        z += d.x * w[8] + d.y * w[9] + d.z * w[10] + d.w * w[11];
        float sig = __fdividef(1.0f, 1.0f + __expf(-z));
        hsum += z * sig;
    }
    g_hsum[(size_t)bi * H + t] = hsum;
}

// ---------------------------------------------------------------------------
// Kernel C: node MLP, 4 nodes per block (amortizes weight-column loads).
//   aug = hsum@W2/99 + b2 + rel_feat@Wr + br
//   p = relu(aug@W3+b3); p = relu(p@W4+b4); pred = p@W5+b5
//   out = inputs + [R@pred[0:3], R@pred[3:6]]
// ---------------------------------------------------------------------------
__device__ __forceinline__ void gemv4(const float sh[4][H],
                                      const float* __restrict__ W, int t,
                                      float acc[4]) {
    acc[0] = 0.f; acc[1] = 0.f; acc[2] = 0.f; acc[3] = 0.f;
    for (int m = 0; m < H; m += 4) {
        float4 ha = *(const float4*)&sh[0][m];
        float4 hb = *(const float4*)&sh[1][m];
        float4 hc = *(const float4*)&sh[2][m];
        float4 hd = *(const float4*)&sh[3][m];
        float w0 = W[(m + 0) * H + t];
        float w1 = W[(m + 1) * H + t];
        float w2 = W[(m + 2) * H + t];
        float w3 = W[(m + 3) * H + t];
        acc[0] += ha.x * w0 + ha.y * w1 + ha.z * w2 + ha.w * w3;
        acc[1] += hb.x * w0 + hb.y * w1 + hb.z * w2 + hb.w * w3;
        acc[2] += hc.x * w0 + hc.y * w1 + hc.z * w2 + hc.w * w3;
        acc[3] += hd.x * w0 + hd.y * w1 + hd.z * w2 + hd.w * w3;
    }
}

__global__ void node_mlp(const float* __restrict__ inputs,
                         const float* __restrict__ W2, const float* __restrict__ b2,
                         const float* __restrict__ Wr, const float* __restrict__ br,
                         const float* __restrict__ W3, const float* __restrict__ b3,
                         const float* __restrict__ W4, const float* __restrict__ b4,
                         const float* __restrict__ W5, const float* __restrict__ b5,
                         float* __restrict__ out, int BN, float inv_cnt) {
    int t = threadIdx.x;
    int n0 = blockIdx.x * 4;
    __shared__ __align__(16) float shA[4][H];
    __shared__ __align__(16) float shB[4][H];
    __shared__ float spred[4][6];

#pragma unroll
    for (int n = 0; n < 4; n++) {
        int node = n0 + n;
        shA[n][t] = (node < BN) ? g_hsum[(size_t)node * H + t] : 0.f;
    }
    __syncthreads();

    float acc[4];
    gemv4(shA, W2, t, acc);

    float wr3 = Wr[3 * H + t], wr4 = Wr[4 * H + t], wr5 = Wr[5 * H + t];
    float bb = b2[t] + br[t];
#pragma unroll
    for (int n = 0; n < 4; n++) {
        int node = n0 + n;
        float aug = 0.f;
        if (node < BN) {
            const float* cv = g_cv + (size_t)node * 3;
            aug = acc[n] * inv_cnt + bb + cv[0] * wr3 + cv[1] * wr4 + cv[2] * wr5;
        }
        shB[n][t] = aug;
    }
    __syncthreads();

    gemv4(shB, W3, t, acc);
    float bias3 = b3[t];
#pragma unroll
    for (int n = 0; n < 4; n++) shA[n][t] = fmaxf(acc[n] + bias3, 0.f);
    __syncthreads();

    gemv4(shA, W4, t, acc);
    float bias4 = b4[t];
#pragma unroll
    for (int n = 0; n < 4; n++) shB[n][t] = fmaxf(acc[n] + bias4, 0.f);
    __syncthreads();

    // pred + rotation + residual: warp wn handles node n0+wn, lanes 0..5
    int wn = t >> 5;
    int lane = t & 31;
    int node = n0 + wn;
    if (lane < 6 && node < BN) {
        float a = b5[lane];
        for (int m = 0; m < H; m++) a += shB[wn][m] * W5[m * 6 + lane];
        spred[wn][lane] = a;
    }
    __syncwarp();
    if (lane < 6 && node < BN) {
        const float* R = g_R + (size_t)node * 9;
        int r = lane % 3;
        int s = (lane / 3) * 3;
        float gl = R[r * 3 + 0] * spred[wn][s + 0] +
                   R[r * 3 + 1] * spred[wn][s + 1] +
                   R[r * 3 + 2] * spred[wn][s + 2];
        out[(size_t)node * 6 + lane] = inputs[(size_t)node * 6 + lane] + gl;
    }
}

// ---------------------------------------------------------------------------
extern "C" void kernel_launch(void* const* d_in, const int* in_sizes, int n_in,
                              void* d_out, int out_size) {
    const float* inputs = (const float*)d_in[0];
    const float* W1 = (const float*)d_in[1];
    const float* b1 = (const float*)d_in[2];
    const float* W2 = (const float*)d_in[3];
    const float* b2 = (const float*)d_in[4];
    const float* Wr = (const float*)d_in[5];
    const float* br = (const float*)d_in[6];
    const float* W3 = (const float*)d_in[7];
    const float* b3 = (const float*)d_in[8];
    const float* W4 = (const float*)d_in[9];
    const float* b4 = (const float*)d_in[10];
    const float* W5 = (const float*)d_in[11];
    const float* b5 = (const float*)d_in[12];

    int E = in_sizes[14];  // recv_edges count = N*(N-1)
    int N = (int)((1.0 + sqrt(1.0 + 4.0 * (double)E)) / 2.0 + 0.5);
    int BN = in_sizes[0] / 6;
    if (N < 2 || N > 128 || BN > MAXBN) return;
    float inv_cnt = 1.0f / (float)(N - 1);

    node_prep<<<(BN + 255) / 256, 256>>>(inputs, BN);
    edge_kernel<<<BN, H>>>(inputs, W1, b1, N);
    node_mlp<<<(BN + 3) / 4, H>>>(inputs, W2, b2, Wr, br, W3, b3, W4, b4,
                                  W5, b5, (float*)d_out, BN, inv_cnt);
}

// round 3
// speedup vs baseline: 1.0706x; 1.0706x over previous
#include <cuda_runtime.h>
#include <math.h>

#define EPSV 1e-7f
#define PI_F 3.14159265358979323846f
#define MAXBN 12800
#define H 128
#define EMAX 128

typedef unsigned long long ull;

// ---- packed f32x2 helpers (sm_100+) --------------------------------------
__device__ __forceinline__ ull pack2(float a, float b) {
    ull r; asm("mov.b64 %0,{%1,%2};" : "=l"(r) : "f"(a), "f"(b)); return r;
}
__device__ __forceinline__ void unpack2(ull v, float& a, float& b) {
    asm("mov.b64 {%0,%1},%2;" : "=f"(a), "=f"(b) : "l"(v));
}
__device__ __forceinline__ ull fma2(ull a, ull b, ull c) {
    ull d; asm("fma.rn.f32x2 %0,%1,%2,%3;" : "=l"(d) : "l"(a), "l"(b), "l"(c)); return d;
}
__device__ __forceinline__ ull mul2(ull a, ull b) {
    ull d; asm("mul.rn.f32x2 %0,%1,%2;" : "=l"(d) : "l"(a), "l"(b)); return d;
}
__device__ __forceinline__ float ex2a(float x) {
    float r; asm("ex2.approx.f32 %0,%1;" : "=f"(r) : "f"(x)); return r;
}
__device__ __forceinline__ float rcpa(float x) {
    float r; asm("rcp.approx.f32 %0,%1;" : "=f"(r) : "f"(x)); return r;
}

#define NL2E -1.4426950408889634f  // -log2(e)

// scratch (static __device__ — no runtime allocation)
__device__ float g_R[MAXBN * 9];
__device__ float g_cv[MAXBN * 3];
__device__ float g_hsum[(size_t)MAXBN * H];

// ---------------------------------------------------------------------------
// Kernel A: per-node rotation matrix + canonical velocity
// ---------------------------------------------------------------------------
__global__ void node_prep(const float* __restrict__ inputs, int BN) {
    int idx = blockIdx.x * blockDim.x + threadIdx.x;
    if (idx >= BN) return;
    const float* x = inputs + (size_t)idx * 6;
    float vx = x[3], vy = x[4], vz = x[5];
    float rho = sqrtf(vx * vx + vy * vy + vz * vz);
    float theta = atan2f(vy, vx);
    float st, ct;
    sincosf(theta, &st, &ct);
    float cpin = fminf(fmaxf(vz / (rho + EPSV), -1.f), 1.f);
    float phi = acosf(cpin);
    float sp, cp;
    sincosf(phi, &sp, &cp);
    float R0 = cp * ct, R1 = -st, R2 = sp * ct;
    float R3 = cp * st, R4 = ct, R5 = sp * st;
    float R6 = -sp, R7 = 0.f, R8 = cp;
    float* Rg = g_R + (size_t)idx * 9;
    Rg[0] = R0; Rg[1] = R1; Rg[2] = R2;
    Rg[3] = R3; Rg[4] = R4; Rg[5] = R5;
    Rg[6] = R6; Rg[7] = R7; Rg[8] = R8;
    float* cv = g_cv + (size_t)idx * 3;
    cv[0] = R0 * vx + R3 * vy + R6 * vz;
    cv[1] = R1 * vx + R4 * vy + R7 * vz;
    cv[2] = R2 * vx + R5 * vy + R8 * vz;
}

// ---------------------------------------------------------------------------
// Kernel B: per (b, recv node) block.
// Phase 1: thread t computes edge t's 12 features, stored FEATURE-MAJOR
//          se[k][t] so phase 2 can read 4 consecutive edges with one LDS.128
//          whose 64-bit halves are ready-made f32x2 operands.
// Phase 2: thread t owns hidden channel t; packed-FMA over edge pairs.
//          Edges padded to multiple of 4 with zero features; the padded
//          silu(base) contributions are subtracted at the end.
// ---------------------------------------------------------------------------
__global__ void edge_kernel(const float* __restrict__ inputs,
                            const float* __restrict__ W1,
                            const float* __restrict__ b1,
                            int N) {
    int bi = blockIdx.x;
    int b = bi / N;
    int i = bi - b * N;
    int t = threadIdx.x;

    __shared__ __align__(16) float se[12][EMAX];

    const float* xi = inputs + (size_t)bi * 6;
    float pix = xi[0], piy = xi[1], piz = xi[2];
    const float* Ri = g_R + (size_t)bi * 9;
    float r0 = Ri[0], r1 = Ri[1], r2 = Ri[2];
    float r3 = Ri[3], r4 = Ri[4], r5 = Ri[5];
    float r6 = Ri[6], r7 = Ri[7], r8 = Ri[8];

    int Em = N - 1;
    int Em_pad = (Em + 3) & ~3;

    if (t < Em) {
        int j = t + (t >= i ? 1 : 0);
        const float* xj = inputs + ((size_t)b * N + j) * 6;
        float relx = xj[0] - pix, rely = xj[1] - piy, relz = xj[2] - piz;
        float rrx = r0 * relx + r3 * rely + r6 * relz;
        float rry = r1 * relx + r4 * rely + r7 * relz;
        float rrz = r2 * relx + r5 * rely + r8 * relz;
        float dist = sqrtf(relx * relx + rely * rely + relz * relz);
        float rho_e = sqrtf(rrx * rrx + rry * rry + rrz * rrz);
        float theta_e = atan2f(rry, rrx);
        float phi_e = acosf(fminf(fmaxf(rrz / (rho_e + EPSV), -1.f), 1.f));
        const float* Rj = g_R + ((size_t)b * N + j) * 9;
        float q0 = Rj[0], q1 = Rj[1], q2 = Rj[2];
        float q3 = Rj[3], q4 = Rj[4], q5 = Rj[5];
        float q6 = Rj[6], q7 = Rj[7], q8 = Rj[8];
        float ro00 = r0 * q0 + r3 * q3 + r6 * q6;
        float ro10 = r1 * q0 + r4 * q3 + r7 * q6;
        float ro20 = r2 * q0 + r5 * q3 + r8 * q6;
        float ro21 = r2 * q1 + r5 * q4 + r8 * q7;
        float ro22 = r2 * q2 + r5 * q5 + r8 * q8;
        float e0 = atan2f(ro10, ro00) * (1.f / PI_F);
        float e1 = asinf(fminf(fmaxf(-ro20, -1.f), 1.f)) * (1.f / PI_F);
        float e2 = atan2f(ro21, ro22) * (1.f / PI_F);
        float vjx = xj[3], vjy = xj[4], vjz = xj[5];
        float rvx = r0 * vjx + r3 * vjy + r6 * vjz;
        float rvy = r1 * vjx + r4 * vjy + r7 * vjz;
        float rvz = r2 * vjx + r5 * vjy + r8 * vjz;
        se[0][t] = rrx;  se[1][t] = rry;   se[2][t] = rrz;
        se[3][t] = e0;   se[4][t] = e1;    se[5][t] = e2;
        se[6][t] = dist; se[7][t] = theta_e; se[8][t] = phi_e;
        se[9][t] = rvx;  se[10][t] = rvy;  se[11][t] = rvz;
    } else if (t < Em_pad) {
#pragma unroll
        for (int k = 0; k < 12; k++) se[k][t] = 0.f;
    }

    // per-channel W1 column, packed (broadcast into both f32x2 halves)
    ull w2[12];
#pragma unroll
    for (int k = 0; k < 12; k++) {
        float w = W1[k * H + t];
        w2[k] = pack2(w, w);
    }
    const float* cv = g_cv + (size_t)bi * 3;
    float base = b1[t] + cv[0] * W1[15 * H + t] + cv[1] * W1[16 * H + t] +
                 cv[2] * W1[17 * H + t];
    ull base2 = pack2(base, base);
    const ull nl2 = pack2(NL2E, NL2E);

    __syncthreads();

    ull hs2 = 0ULL;  // (+0.0f, +0.0f)
    for (int je = 0; je < Em_pad; je += 4) {
        ull zA = base2, zB = base2;
#pragma unroll
        for (int k = 0; k < 12; k++) {
            ulonglong2 p = *(const ulonglong2*)&se[k][je];
            zA = fma2(p.x, w2[k], zA);
            zB = fma2(p.y, w2[k], zB);
        }
        // silu(z) = z * 1/(1 + 2^(-z*log2e)), packed except MUFU
        {
            ull tA = mul2(zA, nl2);
            float t0, t1; unpack2(tA, t0, t1);
            float d0 = ex2a(t0) + 1.f;
            float d1 = ex2a(t1) + 1.f;
            ull rA = pack2(rcpa(d0), rcpa(d1));
            hs2 = fma2(zA, rA, hs2);
        }
        {
            ull tB = mul2(zB, nl2);
            float t0, t1; unpack2(tB, t0, t1);
            float d0 = ex2a(t0) + 1.f;
            float d1 = ex2a(t1) + 1.f;
            ull rB = pack2(rcpa(d0), rcpa(d1));
            hs2 = fma2(zB, rB, hs2);
        }
    }
    float h0, h1;
    unpack2(hs2, h0, h1);
    float hsum = h0 + h1;
    int npad = Em_pad - Em;
    if (npad) {
        float db = ex2a(base * NL2E) + 1.f;
        float sb = base * rcpa(db);
        hsum -= (float)npad * sb;
    }
    g_hsum[(size_t)bi * H + t] = hsum;
}

// ---------------------------------------------------------------------------
// Kernel C: node MLP, 4 nodes per block, packed-f32x2 gemv.
// ---------------------------------------------------------------------------
__device__ __forceinline__ void gemv4p(const float sh[4][H],
                                       const float* __restrict__ W, int t,
                                       float acc[4]) {
    ull a0 = 0ULL, a1 = 0ULL, a2 = 0ULL, a3 = 0ULL;
    for (int m = 0; m < H; m += 4) {
        float w0 = W[(m + 0) * H + t];
        float w1 = W[(m + 1) * H + t];
        float wq2 = W[(m + 2) * H + t];
        float w3 = W[(m + 3) * H + t];
        ull wp0 = pack2(w0, w1);
        ull wp1 = pack2(wq2, w3);
        ulonglong2 h0 = *(const ulonglong2*)&sh[0][m];
        ulonglong2 h1 = *(const ulonglong2*)&sh[1][m];
        ulonglong2 h2 = *(const ulonglong2*)&sh[2][m];
        ulonglong2 h3 = *(const ulonglong2*)&sh[3][m];
        a0 = fma2(h0.x, wp0, a0); a0 = fma2(h0.y, wp1, a0);
        a1 = fma2(h1.x, wp0, a1); a1 = fma2(h1.y, wp1, a1);
        a2 = fma2(h2.x, wp0, a2); a2 = fma2(h2.y, wp1, a2);
        a3 = fma2(h3.x, wp0, a3); a3 = fma2(h3.y, wp1, a3);
    }
    float x, y;
    unpack2(a0, x, y); acc[0] = x + y;
    unpack2(a1, x, y); acc[1] = x + y;
    unpack2(a2, x, y); acc[2] = x + y;
    unpack2(a3, x, y); acc[3] = x + y;
}

__global__ void node_mlp(const float* __restrict__ inputs,
                         const float* __restrict__ W2, const float* __restrict__ b2,
                         const float* __restrict__ Wr, const float* __restrict__ br,
                         const float* __restrict__ W3, const float* __restrict__ b3,
                         const float* __restrict__ W4, const float* __restrict__ b4,
                         const float* __restrict__ W5, const float* __restrict__ b5,
                         float* __restrict__ out, int BN, float inv_cnt) {
    int t = threadIdx.x;
    int n0 = blockIdx.x * 4;
    __shared__ __align__(16) float shA[4][H];
    __shared__ __align__(16) float shB[4][H];
    __shared__ float spred[4][6];

#pragma unroll
    for (int n = 0; n < 4; n++) {
        int node = n0 + n;
        shA[n][t] = (node < BN) ? g_hsum[(size_t)node * H + t] : 0.f;
    }
    __syncthreads();

    float acc[4];
    gemv4p(shA, W2, t, acc);

    float wr3 = Wr[3 * H + t], wr4 = Wr[4 * H + t], wr5 = Wr[5 * H + t];
    float bb = b2[t] + br[t];
#pragma unroll
    for (int n = 0; n < 4; n++) {
        int node = n0 + n;
        float aug = 0.f;
        if (node < BN) {
            const float* cv = g_cv + (size_t)node * 3;
            aug = acc[n] * inv_cnt + bb + cv[0] * wr3 + cv[1] * wr4 + cv[2] * wr5;
        }
        shB[n][t] = aug;
    }
    __syncthreads();

    gemv4p(shB, W3, t, acc);
    float bias3 = b3[t];
#pragma unroll
    for (int n = 0; n < 4; n++) shA[n][t] = fmaxf(acc[n] + bias3, 0.f);
    __syncthreads();

    gemv4p(shA, W4, t, acc);
    float bias4 = b4[t];
#pragma unroll
    for (int n = 0; n < 4; n++) shB[n][t] = fmaxf(acc[n] + bias4, 0.f);
    __syncthreads();

    int wn = t >> 5;
    int lane = t & 31;
    int node = n0 + wn;
    if (lane < 6 && node < BN) {
        float a = b5[lane];
        for (int m = 0; m < H; m++) a += shB[wn][m] * W5[m * 6 + lane];
        spred[wn][lane] = a;
    }
    __syncwarp();
    if (lane < 6 && node < BN) {
        const float* R = g_R + (size_t)node * 9;
        int r = lane % 3;
        int s = (lane / 3) * 3;
        float gl = R[r * 3 + 0] * spred[wn][s + 0] +
                   R[r * 3 + 1] * spred[wn][s + 1] +
                   R[r * 3 + 2] * spred[wn][s + 2];
        out[(size_t)node * 6 + lane] = inputs[(size_t)node * 6 + lane] + gl;
    }
}

// ---------------------------------------------------------------------------
extern "C" void kernel_launch(void* const* d_in, const int* in_sizes, int n_in,
                              void* d_out, int out_size) {
    const float* inputs = (const float*)d_in[0];
    const float* W1 = (const float*)d_in[1];
    const float* b1 = (const float*)d_in[2];
    const float* W2 = (const float*)d_in[3];
    const float* b2 = (const float*)d_in[4];
    const float* Wr = (const float*)d_in[5];
    const float* br = (const float*)d_in[6];
    const float* W3 = (const float*)d_in[7];
    const float* b3 = (const float*)d_in[8];
    const float* W4 = (const float*)d_in[9];
    const float* b4 = (const float*)d_in[10];
    const float* W5 = (const float*)d_in[11];
    const float* b5 = (const float*)d_in[12];

    int E = in_sizes[14];  // recv_edges count = N*(N-1)
    int N = (int)((1.0 + sqrt(1.0 + 4.0 * (double)E)) / 2.0 + 0.5);
    int BN = in_sizes[0] / 6;
    if (N < 2 || N > 128 || BN > MAXBN) return;
    float inv_cnt = 1.0f / (float)(N - 1);

    node_prep<<<(BN + 255) / 256, 256>>>(inputs, BN);
    edge_kernel<<<BN, H>>>(inputs, W1, b1, N);
    node_mlp<<<(BN + 3) / 4, H>>>(inputs, W2, b2, Wr, br, W3, b3, W4, b4,
                                  W5, b5, (float*)d_out, BN, inv_cnt);
}